// round 16
// baseline (speedup 1.0000x reference)
#include <cuda_runtime.h>

// ExpandEvecs: out[b,k,n,m] = sum_{j<=k} ev[b,n,j] * ev[b,m,j]
// ev: [4,1,1024,16] fp32 ; out: [4,16,1024,1024] fp32 (256 MB)
// Wall = 256MB / DRAM-write-BW; best so far k-outer 32KB bursts + __stwt
// (5.38 TB/s). This round: double in-flight WT store depth. A one-time
// transpose pre-kernel (evT[b][k][m], 256KB device scratch) makes the per-k
// B-read ONE warp-coalesced LDG.128, cutting main-kernel regs 128 -> ~50 so
// 4 CTAs/SM fit: grid 512 = one full wave at occ 4, 32 warps/SM.

#define NDIM 1024
#define KDIM 16
#define TILE_N 8

__device__ float g_evT[4 * KDIM * NDIM];   // transposed ev, 256 KB scratch

__global__ void transpose_kernel(const float* __restrict__ ev, int total) {
    int idx = blockIdx.x * blockDim.x + threadIdx.x;   // over b*m*k
    if (idx < total) {
        const int k  = idx & (KDIM - 1);
        const int m  = (idx >> 4) & (NDIM - 1);
        const int b  = idx >> 14;
        g_evT[((size_t)b * KDIM + k) * NDIM + m] = ev[idx];
    }
}

__global__ __launch_bounds__(256, 4)
void expand_evecs_kernel(const float* __restrict__ ev, float* __restrict__ out) {
    const int b   = blockIdx.y;
    const int n0  = blockIdx.x * TILE_N;
    const int tid = threadIdx.x;
    const int m   = tid << 2;                 // 4 consecutive m-cols per thread

    __shared__ float a_s[TILE_N][KDIM];       // 8 x 16 a-rows for this n-tile

    // a-tile: 128 contiguous floats from the original layout.
    if (tid < TILE_N * KDIM)
        a_s[tid >> 4][tid & 15] = ev[(size_t)b * NDIM * KDIM + n0 * KDIM + tid];
    __syncthreads();

    // 8 running cumsum accumulators, one per n-row of the tile.
    float4 acc[TILE_N];
    #pragma unroll
    for (int nn = 0; nn < TILE_N; ++nn)
        acc[nn] = make_float4(0.f, 0.f, 0.f, 0.f);

    const float* evTb = g_evT + (size_t)b * KDIM * NDIM;
    float* op = out + (((size_t)b * KDIM) * NDIM + n0) * NDIM + m;
    const size_t plane = (size_t)NDIM * NDIM;

    #pragma unroll
    for (int k = 0; k < KDIM; ++k) {
        // This thread's 4 B-values for step k: one coalesced L1-hit LDG.128.
        const float4 vb = *(const float4*)(evTb + (size_t)k * NDIM + m);

        // 8 consecutive 4KB rows of plane k -> 32KB contiguous WT burst.
        #pragma unroll
        for (int nn = 0; nn < TILE_N; ++nn) {
            const float ak = a_s[nn][k];      // LDS broadcast
            acc[nn].x = fmaf(ak, vb.x, acc[nn].x);
            acc[nn].y = fmaf(ak, vb.y, acc[nn].y);
            acc[nn].z = fmaf(ak, vb.z, acc[nn].z);
            acc[nn].w = fmaf(ak, vb.w, acc[nn].w);
            __stwt((float4*)(op + (size_t)nn * NDIM), acc[nn]);
        }
        op += plane;
    }
}

extern "C" void kernel_launch(void* const* d_in, const int* in_sizes, int n_in,
                              void* d_out, int out_size) {
    const float* ev = (const float*)d_in[0];
    float* out = (float*)d_out;
    const int B = in_sizes[0] / (NDIM * KDIM);     // = 4
    const int total = B * NDIM * KDIM;             // 65536

    transpose_kernel<<<(total + 255) / 256, 256>>>(ev, total);
    dim3 grid(NDIM / TILE_N, B);                   // 128 x 4 = 512 blocks
    expand_evecs_kernel<<<grid, 256>>>(ev, out);
}

// round 17
// speedup vs baseline: 1.1255x; 1.1255x over previous
#include <cuda_runtime.h>

// ExpandEvecs: out[b,k,n,m] = sum_{j<=k} ev[b,n,j] * ev[b,m,j]
// ev: [4,1,1024,16] fp32 ; out: [4,16,1024,1024] fp32 (256 MB)
// Session finding: achieved HBM write BW drops as resident-stream count
// rises. R17 = locality extreme: ONE CTA per SM (grid 152, wave-1 = 1/SM),
// ~150 clean sequential write streams, zero cross-CTA interleave inside an
// SM. Structure otherwise = R14 champion: k-outer, register-resident
// B-rows, running cumsum, __stwt write-through, 16KB contiguous bursts.

#define NDIM 1024
#define KDIM 16
#define TILE_N 4
#define GRID_BLOCKS 152
#define TILES_PER_B (NDIM / TILE_N)          // 256
#define N_TILES (4 * TILES_PER_B)            // 1024 (b fixed at 4 by problem)

__global__ __launch_bounds__(256, 1)
void expand_evecs_kernel(const float* __restrict__ ev,
                         float* __restrict__ out,
                         int n_tiles) {
    const int tid = threadIdx.x;
    const int m   = tid << 2;                // 4 consecutive m-cols per thread

    // Contiguous chunk of (b, n-tile) work items for this block.
    const int per = n_tiles / GRID_BLOCKS;
    const int rem = n_tiles % GRID_BLOCKS;
    int start, count;
    if ((int)blockIdx.x < rem) { count = per + 1; start = blockIdx.x * count; }
    else { count = per; start = rem * (per + 1) + (blockIdx.x - rem) * per; }

    __shared__ float a_s[TILE_N][KDIM];      // 4 x 16 a-rows, refilled per tile

    float bw[4][KDIM];                       // register-resident B-rows
    int cur_b = -1;

    const size_t plane = (size_t)NDIM * NDIM;

    for (int t = start; t < start + count; ++t) {
        const int b  = t >> 8;               // TILES_PER_B = 256
        const int nt = t & (TILES_PER_B - 1);
        const int n0 = nt * TILE_N;
        const float* evb = ev + (size_t)b * NDIM * KDIM;

        if (b != cur_b) {                    // at most 2 distinct b per block
            const float4* evb4 = (const float4*)evb;
            #pragma unroll
            for (int i = 0; i < 4; ++i) {
                #pragma unroll
                for (int q = 0; q < 4; ++q)
                    ((float4*)bw[i])[q] = evb4[(size_t)(m + i) * (KDIM / 4) + q];
            }
            cur_b = b;
        }

        // a-tile: 64 contiguous floats.
        __syncthreads();                     // protect reuse of a_s
        if (tid < TILE_N * KDIM)
            a_s[tid >> 4][tid & 15] = evb[(size_t)n0 * KDIM + tid];
        __syncthreads();

        float4 acc[TILE_N];
        #pragma unroll
        for (int nn = 0; nn < TILE_N; ++nn)
            acc[nn] = make_float4(0.f, 0.f, 0.f, 0.f);

        float* op = out + (((size_t)b * KDIM) * NDIM + n0) * NDIM + m;

        #pragma unroll
        for (int k = 0; k < KDIM; ++k) {
            // 4 consecutive 4KB rows of plane k -> 16KB contiguous WT burst,
            // emitted by the whole CTA in sequential address order.
            #pragma unroll
            for (int nn = 0; nn < TILE_N; ++nn) {
                const float ak = a_s[nn][k]; // LDS broadcast
                acc[nn].x = fmaf(ak, bw[0][k], acc[nn].x);
                acc[nn].y = fmaf(ak, bw[1][k], acc[nn].y);
                acc[nn].z = fmaf(ak, bw[2][k], acc[nn].z);
                acc[nn].w = fmaf(ak, bw[3][k], acc[nn].w);
                __stwt((float4*)(op + (size_t)nn * NDIM), acc[nn]);
            }
            op += plane;
        }
    }
}

extern "C" void kernel_launch(void* const* d_in, const int* in_sizes, int n_in,
                              void* d_out, int out_size) {
    const float* ev = (const float*)d_in[0];
    float* out = (float*)d_out;
    const int B = in_sizes[0] / (NDIM * KDIM);       // = 4
    const int n_tiles = B * TILES_PER_B;             // 1024
    expand_evecs_kernel<<<GRID_BLOCKS, 256>>>(ev, out, n_tiles);
}